// round 1
// baseline (speedup 1.0000x reference)
#include <cuda_runtime.h>
#include <math.h>

// BinaryTreeLatentVariable: N_LEAVES=1024, L=16, C=4.
// out[node,(lp,cp)] = parent[lp,cp] + mL + mR
//                   + log( sum_{i,j} expT[(lp,cp),i,j] * exp(L[i]-mL) * exp(R[j]-mR) )
// with i=(ll,cl), j=(lr,cr), 64 outputs per node, K=4096 reduction.

#define OC 64      // outputs per node = L*C
#define KD 4096    // 64*64

// Scratch (allocation-free rule: __device__ globals)
__device__ float g_ET[OC * 64 * 64];   // 1 MB: exp(trans) repacked [o][i][j]
__device__ float g_bufA[512 * OC];
__device__ float g_bufB[512 * OC];

// ---------------------------------------------------------------------------
// Prologue: ET[o][i][j] = exp(trans[lp,ll,lr,cp,cl,cr])
// ---------------------------------------------------------------------------
__global__ void expT_kernel(const float* __restrict__ trans) {
    int idx = blockIdx.x * 256 + threadIdx.x;   // 0 .. 262143
    int o = idx >> 12, i = (idx >> 6) & 63, j = idx & 63;
    int lp = o >> 2, cp = o & 3;
    int ll = i >> 2, cl = i & 3;
    int lr = j >> 2, cr = j & 3;
    int src = ((((lp * 16 + ll) * 16 + lr) * 4 + cp) * 4 + cl) * 4 + cr;
    g_ET[idx] = expf(trans[src]);
}

// ---------------------------------------------------------------------------
// One tree level. NB nodes per CTA, 8 warps, each warp owns one output o
// (o = blockIdx.y*8 + warp). Per (o,i): warp loads 64-float ET row (float2 per
// lane, coalesced 256B), FMAs against NB broadcast eL values; eR folded in at
// the end per lane (each lane owns j=2*lane, 2*lane+1), then warp-reduce.
// ---------------------------------------------------------------------------
template <int NB>
__global__ __launch_bounds__(256) void level_kernel(
    const float* __restrict__ leaves,     // child base when child_sel==0
    const float* __restrict__ parent,     // node_state + (n-1)*64
    float* __restrict__ final_out,        // used when out_sel==3
    int n, int child_sel, int out_sel)
{
    __shared__ float eLs[64 * NB];        // [i*NB + nb]   (i-major: broadcast loads)
    __shared__ float eRs[NB * 64];        // [nb*64 + j]
    __shared__ float base_s[NB];          // mL + mR

    const float* child = (child_sel == 0) ? leaves
                        : (child_sel == 1) ? g_bufA : g_bufB;
    float* out = (out_sel == 1) ? g_bufA
               : (out_sel == 2) ? g_bufB : final_out;

    const int tid  = threadIdx.x;
    const int warp = tid >> 5;
    const int lane = tid & 31;
    const int nodeBase = blockIdx.x * NB;

    // ---- load children, per-node max, exp into smem ----
    for (int nb = warp; nb < NB; nb += 8) {
        int node = nodeBase + nb;
        float l0 = -INFINITY, l1 = -INFINITY, r0 = -INFINITY, r1 = -INFINITY;
        if (node < n) {
            const float* L = child + (size_t)(2 * node) * OC;
            const float* R = L + OC;
            l0 = L[lane];      l1 = L[lane + 32];
            r0 = R[lane];      r1 = R[lane + 32];
        }
        float mL = fmaxf(l0, l1), mR = fmaxf(r0, r1);
        #pragma unroll
        for (int s = 16; s > 0; s >>= 1) {
            mL = fmaxf(mL, __shfl_xor_sync(0xffffffffu, mL, s));
            mR = fmaxf(mR, __shfl_xor_sync(0xffffffffu, mR, s));
        }
        if (node < n) {
            eLs[lane * NB + nb]        = __expf(l0 - mL);
            eLs[(lane + 32) * NB + nb] = __expf(l1 - mL);
            eRs[nb * 64 + lane]        = __expf(r0 - mR);
            eRs[nb * 64 + lane + 32]   = __expf(r1 - mR);
        } else {
            eLs[lane * NB + nb] = 0.0f;  eLs[(lane + 32) * NB + nb] = 0.0f;
            eRs[nb * 64 + lane] = 0.0f;  eRs[nb * 64 + lane + 32]   = 0.0f;
            mL = 0.0f; mR = 0.0f;
        }
        if (lane == 0) base_s[nb] = mL + mR;
    }
    __syncthreads();

    const int o = blockIdx.y * 8 + warp;

    float acc0[NB], acc1[NB];
    #pragma unroll
    for (int nb = 0; nb < NB; nb++) { acc0[nb] = 0.0f; acc1[nb] = 0.0f; }

    // ET row pointer for this (o), offset to this lane's j-pair
    const float2* __restrict__ et =
        reinterpret_cast<const float2*>(g_ET + (size_t)o * KD) + lane;

    #pragma unroll 2
    for (int i = 0; i < 64; i++) {
        float2 e = et[i * 32];
        const float* __restrict__ el = &eLs[i * NB];
        #pragma unroll
        for (int nb = 0; nb < NB; nb++) {
            float w = el[nb];
            acc0[nb] = fmaf(e.x, w, acc0[nb]);   // j = 2*lane
            acc1[nb] = fmaf(e.y, w, acc1[nb]);   // j = 2*lane + 1
        }
    }

    // ---- fold eR, warp-reduce, epilogue ----
    #pragma unroll
    for (int nb = 0; nb < NB; nb++) {
        float v = acc0[nb] * eRs[nb * 64 + 2 * lane]
                + acc1[nb] * eRs[nb * 64 + 2 * lane + 1];
        #pragma unroll
        for (int s = 16; s > 0; s >>= 1)
            v += __shfl_xor_sync(0xffffffffu, v, s);
        if (lane == 0) {
            int node = nodeBase + nb;
            if (node < n)
                out[(size_t)node * OC + o] =
                    parent[(size_t)node * OC + o] + base_s[nb] + logf(v);
        }
    }
}

// ---------------------------------------------------------------------------
// Host side
// ---------------------------------------------------------------------------
static void launch_level(int n, int NB, const float* leaves, const float* ns,
                         float* dout, int child_sel, int out_sel)
{
    dim3 grid((n + NB - 1) / NB, 8);
    const float* parent = ns + (size_t)(n - 1) * OC;
    switch (NB) {
        case 16: level_kernel<16><<<grid, 256>>>(leaves, parent, dout, n, child_sel, out_sel); break;
        case 8:  level_kernel<8 ><<<grid, 256>>>(leaves, parent, dout, n, child_sel, out_sel); break;
        case 4:  level_kernel<4 ><<<grid, 256>>>(leaves, parent, dout, n, child_sel, out_sel); break;
        case 2:  level_kernel<2 ><<<grid, 256>>>(leaves, parent, dout, n, child_sel, out_sel); break;
        default: level_kernel<1 ><<<grid, 256>>>(leaves, parent, dout, n, child_sel, out_sel); break;
    }
}

extern "C" void kernel_launch(void* const* d_in, const int* in_sizes, int n_in,
                              void* d_out, int out_size)
{
    const float* node_state = (const float*)d_in[0];
    const float* trans      = (const float*)d_in[1];
    // Defensive: identify by element count (node_state=131008, trans=262144)
    if (n_in >= 2 && in_sizes[0] == 262144) {
        const float* t = node_state; node_state = trans; trans = t;
    }

    // Prologue: 262144 elements
    expT_kernel<<<1024, 256>>>(trans);

    const float* leaves = node_state + (size_t)1023 * OC;  // node_state[1023:2047]
    float* outp = (float*)d_out;

    // schedule: n, NB, child_sel (0=leaves,1=A,2=B), out_sel (1=A,2=B,3=d_out)
    const int sched[10][4] = {
        {512, 16, 0, 1},
        {256, 16, 1, 2},
        {128,  8, 2, 1},
        { 64,  4, 1, 2},
        { 32,  2, 2, 1},
        { 16,  1, 1, 2},
        {  8,  1, 2, 1},
        {  4,  1, 1, 2},
        {  2,  1, 2, 1},
        {  1,  1, 1, 3},
    };
    for (int l = 0; l < 10; l++)
        launch_level(sched[l][0], sched[l][1], leaves, node_state, outp,
                     sched[l][2], sched[l][3]);
}

// round 2
// speedup vs baseline: 1.6175x; 1.6175x over previous
#include <cuda_runtime.h>
#include <math.h>

// BinaryTreeLatentVariable: N_LEAVES=1024, L=16, C=4.
// out[node,o] = parent[node,o] + mL + mR
//             + log( sum_{i,j} expT[o,i,j] * exp(L[i]-mL) * exp(R[j]-mR) )
// o=(lp,cp), i=(ll,cl), j=(lr,cr); 64 outputs/node, K=4096.

#define OC 64
#define KD 4096

__device__ float g_ET[OC * 64 * 64];   // 1 MB: exp(trans) repacked [o][i][j]
__device__ float g_bufA[512 * OC];
__device__ float g_bufB[512 * OC];

// ---------------------------------------------------------------------------
// packed f32x2 fma (Blackwell FFMA2): d = a*b + c per component
// ---------------------------------------------------------------------------
__device__ __forceinline__ float2 ffma2(float2 a, float2 b, float2 c) {
    float2 d;
    asm volatile(
        "{\n\t"
        ".reg .b64 ra, rb, rc, rd;\n\t"
        "mov.b64 ra, {%2, %3};\n\t"
        "mov.b64 rb, {%4, %5};\n\t"
        "mov.b64 rc, {%6, %7};\n\t"
        "fma.rn.f32x2 rd, ra, rb, rc;\n\t"
        "mov.b64 {%0, %1}, rd;\n\t"
        "}"
        : "=f"(d.x), "=f"(d.y)
        : "f"(a.x), "f"(a.y), "f"(b.x), "f"(b.y), "f"(c.x), "f"(c.y));
    return d;
}

// ---------------------------------------------------------------------------
// Prologue: ET[o][i][j] = exp(trans[lp,ll,lr,cp,cl,cr])
// ---------------------------------------------------------------------------
__global__ void expT_kernel(const float* __restrict__ trans) {
    int idx = blockIdx.x * 256 + threadIdx.x;   // 0 .. 262143
    int o = idx >> 12, i = (idx >> 6) & 63, j = idx & 63;
    int lp = o >> 2, cp = o & 3;
    int ll = i >> 2, cl = i & 3;
    int lr = j >> 2, cr = j & 3;
    int src = ((((lp * 16 + ll) * 16 + lr) * 4 + cp) * 4 + cl) * 4 + cr;
    g_ET[idx] = expf(trans[src]);
}

// ---------------------------------------------------------------------------
// One tree level. CTA = 8 warps; warp w owns output o = blockIdx.y*8 + w and
// NB nodes (nodeBase = blockIdx.x*NB). Inner loop over i in chunks of 8 with
// register prefetch (MLP=8), FFMA2 over packed nb-pairs.
// Lane owns j = {2*lane, 2*lane+1}; eR folded at the end, warp-reduce, log.
// ---------------------------------------------------------------------------
template <int NB>
__global__ __launch_bounds__(256) void level_kernel(
    const float* __restrict__ leaves,
    const float* __restrict__ parent,
    float* __restrict__ final_out,
    int n, int child_sel, int out_sel)
{
    static_assert(NB % 2 == 0, "NB must be even for f32x2 packing");
    constexpr int NP = NB / 2;

    __shared__ float eLs[64 * NB];   // [i][nb] — pairs (nb,nb+1) are 8B-contiguous
    __shared__ float eRs[NB * 64];   // [nb][j]
    __shared__ float base_s[NB];     // mL + mR

    const float* child = (child_sel == 0) ? leaves
                        : (child_sel == 1) ? g_bufA : g_bufB;
    float* out = (out_sel == 1) ? g_bufA
               : (out_sel == 2) ? g_bufB : final_out;

    const int tid  = threadIdx.x;
    const int warp = tid >> 5;
    const int lane = tid & 31;
    const int nodeBase = blockIdx.x * NB;

    // ---- children -> per-node max -> exp -> smem ----
    for (int nb = warp; nb < NB; nb += 8) {
        int node = nodeBase + nb;
        float l0 = -INFINITY, l1 = -INFINITY, r0 = -INFINITY, r1 = -INFINITY;
        if (node < n) {
            const float* L = child + (size_t)(2 * node) * OC;
            const float* R = L + OC;
            l0 = L[lane];  l1 = L[lane + 32];
            r0 = R[lane];  r1 = R[lane + 32];
        }
        float mL = fmaxf(l0, l1), mR = fmaxf(r0, r1);
        #pragma unroll
        for (int s = 16; s > 0; s >>= 1) {
            mL = fmaxf(mL, __shfl_xor_sync(0xffffffffu, mL, s));
            mR = fmaxf(mR, __shfl_xor_sync(0xffffffffu, mR, s));
        }
        if (node < n) {
            eLs[lane * NB + nb]        = __expf(l0 - mL);
            eLs[(lane + 32) * NB + nb] = __expf(l1 - mL);
            eRs[nb * 64 + lane]        = __expf(r0 - mR);
            eRs[nb * 64 + lane + 32]   = __expf(r1 - mR);
        } else {
            eLs[lane * NB + nb] = 0.0f;  eLs[(lane + 32) * NB + nb] = 0.0f;
            eRs[nb * 64 + lane] = 0.0f;  eRs[nb * 64 + lane + 32]   = 0.0f;
            mL = 0.0f; mR = 0.0f;
        }
        if (lane == 0) base_s[nb] = mL + mR;
    }
    __syncthreads();

    const int o = blockIdx.y * 8 + warp;

    // Accumulators: A0[p] = (acc_j0[2p], acc_j0[2p+1]), A1[p] same for j1.
    float2 A0[NP], A1[NP];
    #pragma unroll
    for (int p = 0; p < NP; p++) {
        A0[p] = make_float2(0.f, 0.f);
        A1[p] = make_float2(0.f, 0.f);
    }

    // ET row pointer: lane's j-pair within o's [64 i][64 j] slice.
    const float2* __restrict__ et =
        reinterpret_cast<const float2*>(g_ET + (size_t)o * KD) + lane;

    // ---- i-loop, chunks of 8 with register prefetch (MLP = 8) ----
    float2 nxt[8];
    #pragma unroll
    for (int k = 0; k < 8; k++) nxt[k] = et[k * 32];

    #pragma unroll
    for (int c = 0; c < 8; c++) {
        float2 cur[8];
        #pragma unroll
        for (int k = 0; k < 8; k++) cur[k] = nxt[k];
        if (c < 7) {
            #pragma unroll
            for (int k = 0; k < 8; k++) nxt[k] = et[((c + 1) * 8 + k) * 32];
        }
        #pragma unroll
        for (int k = 0; k < 8; k++) {
            const int i = c * 8 + k;
            const float2 e = cur[k];
            const float2 exx = make_float2(e.x, e.x);
            const float2 eyy = make_float2(e.y, e.y);
            const float2* __restrict__ el =
                reinterpret_cast<const float2*>(eLs + i * NB);
            #pragma unroll
            for (int p = 0; p < NP; p++) {
                float2 w = el[p];            // (eL[i,2p], eL[i,2p+1]) — one LDS.64
                A0[p] = ffma2(exx, w, A0[p]);
                A1[p] = ffma2(eyy, w, A1[p]);
            }
        }
    }

    // ---- fold eR, warp-reduce, epilogue ----
    #pragma unroll
    for (int p = 0; p < NP; p++) {
        #pragma unroll
        for (int h = 0; h < 2; h++) {
            const int nb = 2 * p + h;
            const float a0 = h ? A0[p].y : A0[p].x;
            const float a1 = h ? A1[p].y : A1[p].x;
            const float2 er =
                reinterpret_cast<const float2*>(eRs + nb * 64)[lane];
            float v = a0 * er.x + a1 * er.y;
            #pragma unroll
            for (int s = 16; s > 0; s >>= 1)
                v += __shfl_xor_sync(0xffffffffu, v, s);
            if (lane == 0) {
                int node = nodeBase + nb;
                if (node < n)
                    out[(size_t)node * OC + o] =
                        parent[(size_t)node * OC + o] + base_s[nb] + logf(v);
            }
        }
    }
}

// ---------------------------------------------------------------------------
// Host side
// ---------------------------------------------------------------------------
static void launch_level(int n, int NB, const float* leaves, const float* ns,
                         float* dout, int child_sel, int out_sel)
{
    dim3 grid((n + NB - 1) / NB, 8);
    const float* parent = ns + (size_t)(n - 1) * OC;
    switch (NB) {
        case 16: level_kernel<16><<<grid, 256>>>(leaves, parent, dout, n, child_sel, out_sel); break;
        case 8:  level_kernel<8 ><<<grid, 256>>>(leaves, parent, dout, n, child_sel, out_sel); break;
        case 4:  level_kernel<4 ><<<grid, 256>>>(leaves, parent, dout, n, child_sel, out_sel); break;
        default: level_kernel<2 ><<<grid, 256>>>(leaves, parent, dout, n, child_sel, out_sel); break;
    }
}

extern "C" void kernel_launch(void* const* d_in, const int* in_sizes, int n_in,
                              void* d_out, int out_size)
{
    const float* node_state = (const float*)d_in[0];
    const float* trans      = (const float*)d_in[1];
    if (n_in >= 2 && in_sizes[0] == 262144) {   // defensive input identification
        const float* t = node_state; node_state = trans; trans = t;
    }

    expT_kernel<<<1024, 256>>>(trans);

    const float* leaves = node_state + (size_t)1023 * OC;
    float* outp = (float*)d_out;

    // n, NB, child_sel (0=leaves,1=A,2=B), out_sel (1=A,2=B,3=d_out)
    const int sched[10][4] = {
        {512, 16, 0, 1},
        {256,  8, 1, 2},
        {128,  8, 2, 1},
        { 64,  4, 1, 2},
        { 32,  2, 2, 1},
        { 16,  2, 1, 2},
        {  8,  2, 2, 1},
        {  4,  2, 1, 2},
        {  2,  2, 2, 1},
        {  1,  2, 1, 3},
    };
    for (int l = 0; l < 10; l++)
        launch_level(sched[l][0], sched[l][1], leaves, node_state, outp,
                     sched[l][2], sched[l][3]);
}